// round 15
// baseline (speedup 1.0000x reference)
#include <cuda_runtime.h>
#include <cuda_bf16.h>
#include <cuda_fp16.h>
#include <cstdint>

#define NPIX  65536
#define KCODE 1024
#define DDIM  256
#define HW    1024
#define MARGIN 1e-3f
#define CAP   1024          // candidate slots per 32-pixel block
#define NBLK  2048          // NPIX / 32

// ---------------- device scratch (static; no allocs) ----------------
__device__ __align__(128) unsigned char F_tiles[(size_t)512 * 8 * 8192];  // 32MB fp16 latent tiles
__device__ __align__(128) unsigned char E_tiles[(size_t)8 * 8 * 8192];    // 512KB fp16 codebook tiles
__device__ unsigned g_cand[(size_t)NBLK * CAP];   // (pix_local<<16)|code
__device__ float    g_csc[(size_t)NBLK * CAP];    // approx score (esq - 2*dot)
__device__ int      g_ccnt[NBLK];
__device__ float    g_esq[KCODE];
__device__ float    g_loss;

// ---------------- helpers ----------------
__device__ __forceinline__ unsigned f2ord(float f) {
    unsigned u = __float_as_uint(f);
    return (u & 0x80000000u) ? ~u : (u | 0x80000000u);
}
__device__ __forceinline__ float ord2f(unsigned u) {
    unsigned v = (u & 0x80000000u) ? (u & 0x7fffffffu) : ~u;
    return __uint_as_float(v);
}
__device__ __forceinline__ uint32_t smem_u32(const void* p) {
    uint32_t a;
    asm("{ .reg .u64 t; cvta.to.shared.u64 t, %1; cvt.u32.u64 %0, t; }" : "=r"(a) : "l"(p));
    return a;
}
__device__ __forceinline__ uint32_t h2(float a, float b) {
    __half2 h = __float22half2_rn(make_float2(a, b));
    return *reinterpret_cast<uint32_t*>(&h);
}
#define SWZ64(off) ((off) ^ (((off) >> 3) & 0x30u))

#define MBAR_INIT(mb, cnt) \
    asm volatile("mbarrier.init.shared.b64 [%0], %1;" :: "r"(mb), "r"((uint32_t)(cnt)) : "memory")
#define MBAR_EXPECT(mb, tx) \
    asm volatile("mbarrier.arrive.expect_tx.shared.b64 _, [%0], %1;" :: "r"(mb), "r"((uint32_t)(tx)) : "memory")
#define MBAR_ARRIVE(mb) \
    asm volatile("mbarrier.arrive.shared.b64 _, [%0];" :: "r"(mb) : "memory")
#define MBAR_WAIT(mb, ph) do {                                                          \
    uint32_t _m = (mb), _p = (ph), _d;                                                  \
    asm volatile("{\n\t.reg .pred p;\n\t"                                               \
        "mbarrier.try_wait.parity.acquire.cta.shared::cta.b64 p, [%1], %2;\n\t"         \
        "selp.b32 %0, 1, 0, p;\n\t}" : "=r"(_d) : "r"(_m), "r"(_p) : "memory");         \
    if (!_d) {                                                                           \
        asm volatile("{\n\t.reg .pred P1;\n\t"                                           \
            "W_%=:\n\t"                                                                  \
            "mbarrier.try_wait.parity.acquire.cta.shared::cta.b64 P1, [%0], %1, 0x989680;\n\t" \
            "@P1 bra.uni D_%=;\n\t"                                                      \
            "bra.uni W_%=;\n\t"                                                          \
            "D_%=:\n\t}" :: "r"(_m), "r"(_p) : "memory");                                \
    }                                                                                    \
} while (0)

__device__ __forceinline__ void bulk_g2s(uint32_t dst, const void* src, uint32_t bytes, uint32_t mb) {
    asm volatile("cp.async.bulk.shared::cta.global.mbarrier::complete_tx::bytes [%0], [%1], %2, [%3];"
                 :: "r"(dst), "l"(src), "r"(bytes), "r"(mb) : "memory");
}
__device__ __forceinline__ void ldsm4(uint32_t* r, uint32_t addr) {
    asm volatile("ldmatrix.sync.aligned.m8n8.x4.shared.b16 {%0,%1,%2,%3}, [%4];"
                 : "=r"(r[0]), "=r"(r[1]), "=r"(r[2]), "=r"(r[3]) : "r"(addr));
}
// fp16 inputs, fp16 accumulate
__device__ __forceinline__ void mma16816h(uint32_t* c, const uint32_t* a, uint32_t b0, uint32_t b1) {
    asm volatile("mma.sync.aligned.m16n8k16.row.col.f16.f16.f16.f16 "
                 "{%0,%1}, {%2,%3,%4,%5}, {%6,%7}, {%0,%1};"
                 : "+r"(c[0]), "+r"(c[1])
                 : "r"(a[0]), "r"(a[1]), "r"(a[2]), "r"(a[3]), "r"(b0), "r"(b1));
}

// ---------------- ||e||^2 + counter init (merged) ----------------
__global__ void k_esq(const float* __restrict__ emb) {
    int gt = blockIdx.x * 256 + threadIdx.x;
    if (gt < NBLK) g_ccnt[gt] = 0;
    if (gt == 0) g_loss = 0.f;
    int w = gt >> 5, lane = gt & 31;
    const float* row = emb + (size_t)w * DDIM;
    float s = 0.f;
#pragma unroll
    for (int j = 0; j < 8; ++j) { float v = row[lane + 32 * j]; s = fmaf(v, v, s); }
#pragma unroll
    for (int sh = 16; sh; sh >>= 1) s += __shfl_xor_sync(0xffffffffu, s, sh);
    if (lane == 0) g_esq[w] = s;
}

// embedding -> blocked swizzled fp16 tiles. grid (8 cblk, 8 kiter), 256 thr.
__global__ void k_prep_emb(const float* __restrict__ emb) {
    int c0 = blockIdx.x << 7, d0 = blockIdx.y << 5;
    unsigned char* dst = E_tiles + ((size_t)(blockIdx.x * 8 + blockIdx.y)) * 8192;
    int t = threadIdx.x;
#pragma unroll
    for (int i = 0; i < 2; ++i) {
        int u = t + (i << 8);
        int r = u >> 2, c8 = (u & 3) << 3;
        const float* src = emb + (size_t)(c0 + r) * DDIM + d0 + c8;
        float4 v0 = *(const float4*)src;
        float4 v1 = *(const float4*)(src + 4);
        uint4 o;
        o.x = h2(v0.x, v0.y); o.y = h2(v0.z, v0.w);
        o.z = h2(v1.x, v1.y); o.w = h2(v1.z, v1.w);
        *(uint4*)(dst + SWZ64((uint32_t)(u << 4))) = o;
    }
}

// latents -> transposed blocked swizzled fp16 tiles. grid (512 tiles, 8 kiter).
__global__ void k_prep_lat(const float* __restrict__ lat) {
    __shared__ float ts[32][129];
    int tile = blockIdx.x, kit = blockIdx.y;
    int b = tile >> 3, p0 = (tile & 7) << 7, d0 = kit << 5;
    int t = threadIdx.x;
#pragma unroll
    for (int i = 0; i < 4; ++i) {
        int u = t + (i << 8);
        int r = u >> 5, c4 = (u & 31) << 2;
        float4 v = *(const float4*)(lat + (((size_t)(b * 256 + d0 + r)) << 10) + p0 + c4);
        ts[r][c4] = v.x; ts[r][c4 + 1] = v.y; ts[r][c4 + 2] = v.z; ts[r][c4 + 3] = v.w;
    }
    __syncthreads();
    unsigned char* dst = F_tiles + ((size_t)(tile * 8 + kit)) * 8192;
#pragma unroll
    for (int i = 0; i < 2; ++i) {
        int u = t + (i << 8);
        int p = u >> 2, c8 = (u & 3) << 3;
        uint4 o;
        o.x = h2(ts[c8][p],     ts[c8 + 1][p]);
        o.y = h2(ts[c8 + 2][p], ts[c8 + 3][p]);
        o.z = h2(ts[c8 + 4][p], ts[c8 + 5][p]);
        o.w = h2(ts[c8 + 6][p], ts[c8 + 7][p]);
        *(uint4*)(dst + SWZ64((uint32_t)(u << 4))) = o;
    }
}

// ---------------- fp16 HMMA GEMM: 16 warps/CTA (32x32 warp tiles), 4-stage pipeline (R13-verified) ----------------
__global__ void __launch_bounds__(512, 2)
k_dist(int toff) {
    extern __shared__ __align__(128) unsigned char buf[];   // 4 x 16384
    __shared__ __align__(8) unsigned long long barF[4];
    __shared__ __align__(8) unsigned long long barE[4];
    __shared__ float s_esq[128];
    __shared__ unsigned s_pmin[128];

    const int tid = threadIdx.x;
    const int lane = tid & 31, wid = tid >> 5;          // 16 warps
    const int cblk = blockIdx.x, tile = blockIdx.y + toff;
    const int n0 = cblk << 7;
    const int wm = (wid & 3) << 5, wn = (wid >> 2) << 5; // 4x4 warp grid, 32x32 tiles
    const int rl = lane & 15;
    const uint32_t ch = (uint32_t)((lane >> 4) << 4);
    const int g = lane >> 2, tg = lane & 3;

    uint32_t qa[2], qb[2];
#pragma unroll
    for (int i = 0; i < 2; ++i) {
        uint32_t row = (uint32_t)(wm + (i << 4) + rl);
        qa[i] = ((row << 6) ^ ((row & 6u) << 3)) ^ ch;
    }
#pragma unroll
    for (int j = 0; j < 2; ++j) {
        uint32_t row = (uint32_t)(wn + (j << 4) + rl);
        qb[j] = ((row << 6) ^ ((row & 6u) << 3)) ^ ch;
    }

    if (tid < 128) { s_esq[tid] = g_esq[n0 + tid]; s_pmin[tid] = ~0u; }
    if (tid == 0) {
#pragma unroll
        for (int s = 0; s < 4; ++s) {
            MBAR_INIT(smem_u32(&barF[s]), 1);
            MBAR_INIT(smem_u32(&barE[s]), 16);
        }
    }
    __syncthreads();
    const uint32_t base = smem_u32(buf);
    if (tid == 0) {
#pragma unroll
        for (int s = 0; s < 4; ++s) {
            uint32_t mb = smem_u32(&barF[s]);
            MBAR_EXPECT(mb, 16384);
            bulk_g2s(base + s * 16384,        F_tiles + ((size_t)(tile * 8 + s)) * 8192, 8192, mb);
            bulk_g2s(base + s * 16384 + 8192, E_tiles + ((size_t)(cblk * 8 + s)) * 8192, 8192, mb);
        }
    }

    uint32_t acc[2][4][2];
#pragma unroll
    for (int i = 0; i < 2; ++i)
#pragma unroll
        for (int j = 0; j < 4; ++j) { acc[i][j][0] = 0u; acc[i][j][1] = 0u; }

    for (int k = 0; k < 8; ++k) {
        const int st = k & 3;
        MBAR_WAIT(smem_u32(&barF[st]), (k >> 2) & 1);
        const uint32_t As = base + st * 16384;
#pragma unroll
        for (int s = 0; s < 2; ++s) {
            const uint32_t soff = (uint32_t)(s << 5);
            uint32_t af[2][4], bf[2][4];
#pragma unroll
            for (int i = 0; i < 2; ++i) ldsm4(af[i], As + (qa[i] ^ soff));
#pragma unroll
            for (int j = 0; j < 2; ++j) ldsm4(bf[j], As + 8192 + (qb[j] ^ soff));
#pragma unroll
            for (int i = 0; i < 2; ++i)
#pragma unroll
                for (int j = 0; j < 2; ++j) {
                    mma16816h(acc[i][2 * j],     af[i], bf[j][0], bf[j][2]);
                    mma16816h(acc[i][2 * j + 1], af[i], bf[j][1], bf[j][3]);
                }
        }
        if (lane == 0) MBAR_ARRIVE(smem_u32(&barE[st]));
        if (tid == 0 && k < 4) {
            MBAR_WAIT(smem_u32(&barE[st]), 0);
            uint32_t mb = smem_u32(&barF[st]);
            MBAR_EXPECT(mb, 16384);
            bulk_g2s(base + st * 16384,        F_tiles + ((size_t)(tile * 8 + k + 4)) * 8192, 8192, mb);
            bulk_g2s(base + st * 16384 + 8192, E_tiles + ((size_t)(cblk * 8 + k + 4)) * 8192, 8192, mb);
        }
    }

    // ---- epilogue: CTA-local per-pixel min, then candidate append ----
    const float INF = __int_as_float(0x7f800000);
    float mr[2][2] = { { INF, INF }, { INF, INF } };
#pragma unroll
    for (int i = 0; i < 2; ++i)
#pragma unroll
        for (int j = 0; j < 4; ++j) {
            const int col0 = wn + ((j >> 1) << 4) + ((j & 1) << 3) + (tg << 1);
            const float e0 = s_esq[col0], e1 = s_esq[col0 + 1];
            float2 lo = __half22float2(*reinterpret_cast<__half2*>(&acc[i][j][0]));
            float2 hi = __half22float2(*reinterpret_cast<__half2*>(&acc[i][j][1]));
            mr[i][0] = fminf(mr[i][0], fminf(fmaf(-2.f, lo.x, e0), fmaf(-2.f, lo.y, e1)));
            mr[i][1] = fminf(mr[i][1], fminf(fmaf(-2.f, hi.x, e0), fmaf(-2.f, hi.y, e1)));
        }
#pragma unroll
    for (int i = 0; i < 2; ++i)
#pragma unroll
        for (int h = 0; h < 2; ++h) {
            float m = mr[i][h];
            m = fminf(m, __shfl_xor_sync(0xffffffffu, m, 1));
            m = fminf(m, __shfl_xor_sync(0xffffffffu, m, 2));
            if (tg == 0) atomicMin(&s_pmin[wm + (i << 4) + (h << 3) + g], f2ord(m));
        }
    __syncthreads();

    float thr[2][2];
#pragma unroll
    for (int i = 0; i < 2; ++i)
#pragma unroll
        for (int h = 0; h < 2; ++h)
            thr[i][h] = ord2f(s_pmin[wm + (i << 4) + (h << 3) + g]) + MARGIN;

    const int blk = (tile << 2) + (wid & 3);
#pragma unroll
    for (int i = 0; i < 2; ++i)
#pragma unroll
        for (int j = 0; j < 4; ++j) {
            const int col0 = wn + ((j >> 1) << 4) + ((j & 1) << 3) + (tg << 1);
            const float e0 = s_esq[col0], e1 = s_esq[col0 + 1];
            float2 lo = __half22float2(*reinterpret_cast<__half2*>(&acc[i][j][0]));
            float2 hi = __half22float2(*reinterpret_cast<__half2*>(&acc[i][j][1]));
            float cv[2][2] = { { lo.x, lo.y }, { hi.x, hi.y } };
#pragma unroll
            for (int h = 0; h < 2; ++h) {
                const int lr = (i << 4) + (h << 3) + g;
                float s0 = fmaf(-2.f, cv[h][0], e0);
                float s1 = fmaf(-2.f, cv[h][1], e1);
                if (s0 <= thr[i][h]) {
                    int idx = atomicAdd(&g_ccnt[blk], 1);
                    if (idx < CAP) {
                        g_cand[(size_t)blk * CAP + idx] = ((unsigned)lr << 16) | (unsigned)(n0 + col0);
                        g_csc[(size_t)blk * CAP + idx] = s0;
                    }
                }
                if (s1 <= thr[i][h]) {
                    int idx = atomicAdd(&g_ccnt[blk], 1);
                    if (idx < CAP) {
                        g_cand[(size_t)blk * CAP + idx] = ((unsigned)lr << 16) | (unsigned)(n0 + col0 + 1);
                        g_csc[(size_t)blk * CAP + idx] = s1;
                    }
                }
            }
        }
}

// ---------------- select + exact rescore + gather + output + MSE (R13-verified slim) ----------------
__global__ void __launch_bounds__(256)
k_select(const float* __restrict__ lat, const float* __restrict__ emb,
         float* __restrict__ out, int boff) {
    extern __shared__ float sm_f[];    // [256 dims][stride 33]; overwritten by quant in phase 2
    __shared__ unsigned long long s_keys[32];
    __shared__ unsigned s_amin[32];
    __shared__ float s_sf[32];
    __shared__ int sInd[32];

    const int t = threadIdx.x;
    const int b2 = blockIdx.x + boff;
    const int p0g = b2 << 5;
    const int b = p0g >> 10, p0 = p0g & 1023;

    if (t < 32) { s_keys[t] = ~0ULL; s_amin[t] = ~0u; }
#pragma unroll
    for (int i = 0; i < 32; ++i) {
        int d = (i << 3) + (t >> 5), px = t & 31;
        sm_f[d * 33 + px] = lat[(((size_t)(b * 256 + d)) << 10) + p0 + px];
    }
    __syncthreads();

    if (t < 32) {
        float s = 0.f;
#pragma unroll 4
        for (int d = 0; d < DDIM; ++d) { float v = sm_f[d * 33 + t]; s = fmaf(v, v, s); }
        s_sf[t] = s;
    }
    const int cnt = min(g_ccnt[b2], CAP);

    for (int c = t; c < cnt; c += 256) {
        unsigned e = g_cand[(size_t)b2 * CAP + c];
        atomicMin(&s_amin[e >> 16], f2ord(g_csc[(size_t)b2 * CAP + c]));
    }
    __syncthreads();

    for (int c = t; c < cnt; c += 256) {
        unsigned e = g_cand[(size_t)b2 * CAP + c];
        int px = e >> 16, code = e & 1023;
        float ap = g_csc[(size_t)b2 * CAP + c];
        if (ap <= ord2f(s_amin[px]) + MARGIN) {
            const float4* er = reinterpret_cast<const float4*>(emb + ((size_t)code << 8));
            const float* fcol = sm_f + px;
            float a0 = 0.f, a1 = 0.f, a2 = 0.f, a3 = 0.f;
#pragma unroll 8
            for (int d4 = 0; d4 < 64; ++d4) {
                float4 e4 = __ldg(er + d4);
                int d = d4 << 2;
                a0 = fmaf(fcol[(d    ) * 33], e4.x, a0);
                a1 = fmaf(fcol[(d + 1) * 33], e4.y, a1);
                a2 = fmaf(fcol[(d + 2) * 33], e4.z, a2);
                a3 = fmaf(fcol[(d + 3) * 33], e4.w, a3);
            }
            float dot = (a0 + a1) + (a2 + a3);
            float sx = fmaf(-2.f, dot, s_sf[px] + g_esq[code]);  // exact reference chain
            unsigned long long key = ((unsigned long long)f2ord(sx) << 32) | (unsigned)code;
            atomicMin(&s_keys[px], key);
        }
    }
    __syncthreads();

    if (t < 32) sInd[t] = (int)(unsigned)s_keys[t];
    __syncthreads();

    float accl = 0.f;
#pragma unroll
    for (int i = 0; i < 8; ++i) {
        int idx4 = t + (i << 8);
        int r = idx4 >> 6, c4 = (idx4 & 63) << 2;
        float4 q = *(const float4*)(emb + (size_t)sInd[r] * DDIM + c4);
        float l0 = sm_f[(c4    ) * 33 + r];
        float l1 = sm_f[(c4 + 1) * 33 + r];
        float l2 = sm_f[(c4 + 2) * 33 + r];
        float l3 = sm_f[(c4 + 3) * 33 + r];
        float d0 = q.x - l0, d1 = q.y - l1, d2 = q.z - l2, d3 = q.w - l3;
        accl = fmaf(d0, d0, accl); accl = fmaf(d1, d1, accl);
        accl = fmaf(d2, d2, accl); accl = fmaf(d3, d3, accl);
        sm_f[(c4    ) * 33 + r] = q.x;
        sm_f[(c4 + 1) * 33 + r] = q.y;
        sm_f[(c4 + 2) * 33 + r] = q.z;
        sm_f[(c4 + 3) * 33 + r] = q.w;
    }
#pragma unroll
    for (int sh = 16; sh; sh >>= 1) accl += __shfl_xor_sync(0xffffffffu, accl, sh);
    if ((t & 31) == 0) atomicAdd(&g_loss, accl);
    __syncthreads();

    const int i2 = t & 31, db = t >> 5;
#pragma unroll
    for (int dd = 0; dd < 32; ++dd) {
        int d = (dd << 3) + db;
        size_t gi = ((size_t)(b * DDIM + d)) * HW + p0 + i2;
        out[gi] = sm_f[d * 33 + i2];
    }
}

__global__ void k_final(float* __restrict__ out, int off) {
    float S = g_loss * (1.0f / 16777216.0f);
    out[off]     = S;
    out[off + 1] = 0.25f * S;
}

// ---------------- streams/events, created once at static-init (pre-main) ----------------
struct StreamInit {
    cudaStream_t s2;
    cudaEvent_t e0, e1, eA, eS;
    StreamInit() {
        cudaStreamCreateWithFlags(&s2, cudaStreamNonBlocking);
        cudaEventCreateWithFlags(&e0, cudaEventDisableTiming);
        cudaEventCreateWithFlags(&e1, cudaEventDisableTiming);
        cudaEventCreateWithFlags(&eA, cudaEventDisableTiming);
        cudaEventCreateWithFlags(&eS, cudaEventDisableTiming);
    }
};
static StreamInit g_si;

extern "C" void kernel_launch(void* const* d_in, const int* in_sizes, int n_in,
                              void* d_out, int out_size) {
    const float* lat = (const float*)d_in[0];
    const float* emb = (const float*)d_in[1];
    float* out = (float*)d_out;

    static const int DYN_SEL = 256 * 33 * 4;   // 33792 B
    static const int DYN_DIST = 4 * 16384;     // 65536 B
    cudaFuncSetAttribute(k_select, cudaFuncAttributeMaxDynamicSharedMemorySize, DYN_SEL);
    cudaFuncSetAttribute(k_dist, cudaFuncAttributeMaxDynamicSharedMemorySize, DYN_DIST);

    // fork: small prep on side stream, big prep on main stream
    cudaEventRecord(g_si.e0, 0);
    cudaStreamWaitEvent(g_si.s2, g_si.e0, 0);
    k_esq<<<KCODE / 8, 256, 0, g_si.s2>>>(emb);
    k_prep_emb<<<dim3(8, 8), 256, 0, g_si.s2>>>(emb);
    cudaEventRecord(g_si.e1, g_si.s2);

    k_prep_lat<<<dim3(512, 8), 256>>>(lat);
    cudaStreamWaitEvent(0, g_si.e1, 0);     // join preps

    // dist half A, then half B overlapped with select half A
    k_dist<<<dim3(8, 256), 512, DYN_DIST>>>(0);
    cudaEventRecord(g_si.eA, 0);
    k_dist<<<dim3(8, 256), 512, DYN_DIST>>>(256);

    cudaStreamWaitEvent(g_si.s2, g_si.eA, 0);
    k_select<<<1024, 256, DYN_SEL, g_si.s2>>>(lat, emb, out, 0);
    cudaEventRecord(g_si.eS, g_si.s2);

    k_select<<<1024, 256, DYN_SEL>>>(lat, emb, out, 1024);
    cudaStreamWaitEvent(0, g_si.eS, 0);     // join selectA before final

    if (out_size >= NPIX * DDIM + 2) {
        k_final<<<1, 1>>>(out, out_size - 2);
    }
}

// round 16
// speedup vs baseline: 1.0149x; 1.0149x over previous
#include <cuda_runtime.h>
#include <cuda_bf16.h>
#include <cuda_fp16.h>
#include <cstdint>

#define NPIX  65536
#define KCODE 1024
#define DDIM  256
#define HW    1024
#define MARGIN 1e-3f
#define CAP   1024          // candidate slots per 32-pixel block
#define NBLK  2048          // NPIX / 32

// ---------------- device scratch (static; no allocs) ----------------
__device__ __align__(128) unsigned char F_tiles[(size_t)512 * 8 * 8192];  // 32MB fp16 latent tiles
__device__ __align__(128) unsigned char E_tiles[(size_t)8 * 8 * 8192];    // 512KB fp16 codebook tiles
__device__ unsigned g_cand[(size_t)NBLK * CAP];   // (pix_local<<16)|code
__device__ float    g_csc[(size_t)NBLK * CAP];    // approx score (esq - 2*dot)
__device__ int      g_ccnt[NBLK];
__device__ float    g_esq[KCODE];
__device__ float    g_loss;

// ---------------- helpers ----------------
__device__ __forceinline__ unsigned f2ord(float f) {
    unsigned u = __float_as_uint(f);
    return (u & 0x80000000u) ? ~u : (u | 0x80000000u);
}
__device__ __forceinline__ float ord2f(unsigned u) {
    unsigned v = (u & 0x80000000u) ? (u & 0x7fffffffu) : ~u;
    return __uint_as_float(v);
}
__device__ __forceinline__ uint32_t smem_u32(const void* p) {
    uint32_t a;
    asm("{ .reg .u64 t; cvta.to.shared.u64 t, %1; cvt.u32.u64 %0, t; }" : "=r"(a) : "l"(p));
    return a;
}
__device__ __forceinline__ uint32_t h2(float a, float b) {
    __half2 h = __float22half2_rn(make_float2(a, b));
    return *reinterpret_cast<uint32_t*>(&h);
}
#define SWZ64(off) ((off) ^ (((off) >> 3) & 0x30u))

#define MBAR_INIT(mb, cnt) \
    asm volatile("mbarrier.init.shared.b64 [%0], %1;" :: "r"(mb), "r"((uint32_t)(cnt)) : "memory")
#define MBAR_EXPECT(mb, tx) \
    asm volatile("mbarrier.arrive.expect_tx.shared.b64 _, [%0], %1;" :: "r"(mb), "r"((uint32_t)(tx)) : "memory")
#define MBAR_ARRIVE(mb) \
    asm volatile("mbarrier.arrive.shared.b64 _, [%0];" :: "r"(mb) : "memory")
#define MBAR_WAIT(mb, ph) do {                                                          \
    uint32_t _m = (mb), _p = (ph), _d;                                                  \
    asm volatile("{\n\t.reg .pred p;\n\t"                                               \
        "mbarrier.try_wait.parity.acquire.cta.shared::cta.b64 p, [%1], %2;\n\t"         \
        "selp.b32 %0, 1, 0, p;\n\t}" : "=r"(_d) : "r"(_m), "r"(_p) : "memory");         \
    if (!_d) {                                                                           \
        asm volatile("{\n\t.reg .pred P1;\n\t"                                           \
            "W_%=:\n\t"                                                                  \
            "mbarrier.try_wait.parity.acquire.cta.shared::cta.b64 P1, [%0], %1, 0x989680;\n\t" \
            "@P1 bra.uni D_%=;\n\t"                                                      \
            "bra.uni W_%=;\n\t"                                                          \
            "D_%=:\n\t}" :: "r"(_m), "r"(_p) : "memory");                                \
    }                                                                                    \
} while (0)

__device__ __forceinline__ void bulk_g2s(uint32_t dst, const void* src, uint32_t bytes, uint32_t mb) {
    asm volatile("cp.async.bulk.shared::cta.global.mbarrier::complete_tx::bytes [%0], [%1], %2, [%3];"
                 :: "r"(dst), "l"(src), "r"(bytes), "r"(mb) : "memory");
}
__device__ __forceinline__ void ldsm4(uint32_t* r, uint32_t addr) {
    asm volatile("ldmatrix.sync.aligned.m8n8.x4.shared.b16 {%0,%1,%2,%3}, [%4];"
                 : "=r"(r[0]), "=r"(r[1]), "=r"(r[2]), "=r"(r[3]) : "r"(addr));
}
// fp16 inputs, fp16 accumulate
__device__ __forceinline__ void mma16816h(uint32_t* c, const uint32_t* a, uint32_t b0, uint32_t b1) {
    asm volatile("mma.sync.aligned.m16n8k16.row.col.f16.f16.f16.f16 "
                 "{%0,%1}, {%2,%3,%4,%5}, {%6,%7}, {%0,%1};"
                 : "+r"(c[0]), "+r"(c[1])
                 : "r"(a[0]), "r"(a[1]), "r"(a[2]), "r"(a[3]), "r"(b0), "r"(b1));
}

// ---------------- ||e||^2 + counter init (merged) ----------------
__global__ void k_esq(const float* __restrict__ emb) {
    int gt = blockIdx.x * 256 + threadIdx.x;
    if (gt < NBLK) g_ccnt[gt] = 0;
    if (gt == 0) g_loss = 0.f;
    int w = gt >> 5, lane = gt & 31;
    const float* row = emb + (size_t)w * DDIM;
    float s = 0.f;
#pragma unroll
    for (int j = 0; j < 8; ++j) { float v = row[lane + 32 * j]; s = fmaf(v, v, s); }
#pragma unroll
    for (int sh = 16; sh; sh >>= 1) s += __shfl_xor_sync(0xffffffffu, s, sh);
    if (lane == 0) g_esq[w] = s;
}

// embedding -> blocked swizzled fp16 tiles. grid (8 cblk, 8 kiter), 256 thr.
__global__ void k_prep_emb(const float* __restrict__ emb) {
    int c0 = blockIdx.x << 7, d0 = blockIdx.y << 5;
    unsigned char* dst = E_tiles + ((size_t)(blockIdx.x * 8 + blockIdx.y)) * 8192;
    int t = threadIdx.x;
#pragma unroll
    for (int i = 0; i < 2; ++i) {
        int u = t + (i << 8);
        int r = u >> 2, c8 = (u & 3) << 3;
        const float* src = emb + (size_t)(c0 + r) * DDIM + d0 + c8;
        float4 v0 = *(const float4*)src;
        float4 v1 = *(const float4*)(src + 4);
        uint4 o;
        o.x = h2(v0.x, v0.y); o.y = h2(v0.z, v0.w);
        o.z = h2(v1.x, v1.y); o.w = h2(v1.z, v1.w);
        *(uint4*)(dst + SWZ64((uint32_t)(u << 4))) = o;
    }
}

// latents -> transposed blocked swizzled fp16 tiles. grid (512 tiles, 8 kiter).
__global__ void k_prep_lat(const float* __restrict__ lat) {
    __shared__ float ts[32][129];
    int tile = blockIdx.x, kit = blockIdx.y;
    int b = tile >> 3, p0 = (tile & 7) << 7, d0 = kit << 5;
    int t = threadIdx.x;
#pragma unroll
    for (int i = 0; i < 4; ++i) {
        int u = t + (i << 8);
        int r = u >> 5, c4 = (u & 31) << 2;
        float4 v = *(const float4*)(lat + (((size_t)(b * 256 + d0 + r)) << 10) + p0 + c4);
        ts[r][c4] = v.x; ts[r][c4 + 1] = v.y; ts[r][c4 + 2] = v.z; ts[r][c4 + 3] = v.w;
    }
    __syncthreads();
    unsigned char* dst = F_tiles + ((size_t)(tile * 8 + kit)) * 8192;
#pragma unroll
    for (int i = 0; i < 2; ++i) {
        int u = t + (i << 8);
        int p = u >> 2, c8 = (u & 3) << 3;
        uint4 o;
        o.x = h2(ts[c8][p],     ts[c8 + 1][p]);
        o.y = h2(ts[c8 + 2][p], ts[c8 + 3][p]);
        o.z = h2(ts[c8 + 4][p], ts[c8 + 5][p]);
        o.w = h2(ts[c8 + 6][p], ts[c8 + 7][p]);
        *(uint4*)(dst + SWZ64((uint32_t)(u << 4))) = o;
    }
}

// ---------------- fp16 HMMA GEMM: 16 warps/CTA (32x32 warp tiles), 4-stage pipeline (R13-verified) ----------------
__global__ void __launch_bounds__(512, 2)
k_dist() {
    extern __shared__ __align__(128) unsigned char buf[];   // 4 x 16384
    __shared__ __align__(8) unsigned long long barF[4];
    __shared__ __align__(8) unsigned long long barE[4];
    __shared__ float s_esq[128];
    __shared__ unsigned s_pmin[128];

    const int tid = threadIdx.x;
    const int lane = tid & 31, wid = tid >> 5;          // 16 warps
    const int cblk = blockIdx.x, tile = blockIdx.y;
    const int n0 = cblk << 7;
    const int wm = (wid & 3) << 5, wn = (wid >> 2) << 5; // 4x4 warp grid, 32x32 tiles
    const int rl = lane & 15;
    const uint32_t ch = (uint32_t)((lane >> 4) << 4);
    const int g = lane >> 2, tg = lane & 3;

    uint32_t qa[2], qb[2];
#pragma unroll
    for (int i = 0; i < 2; ++i) {
        uint32_t row = (uint32_t)(wm + (i << 4) + rl);
        qa[i] = ((row << 6) ^ ((row & 6u) << 3)) ^ ch;
    }
#pragma unroll
    for (int j = 0; j < 2; ++j) {
        uint32_t row = (uint32_t)(wn + (j << 4) + rl);
        qb[j] = ((row << 6) ^ ((row & 6u) << 3)) ^ ch;
    }

    if (tid < 128) { s_esq[tid] = g_esq[n0 + tid]; s_pmin[tid] = ~0u; }
    if (tid == 0) {
#pragma unroll
        for (int s = 0; s < 4; ++s) {
            MBAR_INIT(smem_u32(&barF[s]), 1);
            MBAR_INIT(smem_u32(&barE[s]), 16);
        }
    }
    __syncthreads();
    const uint32_t base = smem_u32(buf);
    if (tid == 0) {
#pragma unroll
        for (int s = 0; s < 4; ++s) {
            uint32_t mb = smem_u32(&barF[s]);
            MBAR_EXPECT(mb, 16384);
            bulk_g2s(base + s * 16384,        F_tiles + ((size_t)(tile * 8 + s)) * 8192, 8192, mb);
            bulk_g2s(base + s * 16384 + 8192, E_tiles + ((size_t)(cblk * 8 + s)) * 8192, 8192, mb);
        }
    }

    uint32_t acc[2][4][2];
#pragma unroll
    for (int i = 0; i < 2; ++i)
#pragma unroll
        for (int j = 0; j < 4; ++j) { acc[i][j][0] = 0u; acc[i][j][1] = 0u; }

    for (int k = 0; k < 8; ++k) {
        const int st = k & 3;
        MBAR_WAIT(smem_u32(&barF[st]), (k >> 2) & 1);
        const uint32_t As = base + st * 16384;
#pragma unroll
        for (int s = 0; s < 2; ++s) {
            const uint32_t soff = (uint32_t)(s << 5);
            uint32_t af[2][4], bf[2][4];
#pragma unroll
            for (int i = 0; i < 2; ++i) ldsm4(af[i], As + (qa[i] ^ soff));
#pragma unroll
            for (int j = 0; j < 2; ++j) ldsm4(bf[j], As + 8192 + (qb[j] ^ soff));
#pragma unroll
            for (int i = 0; i < 2; ++i)
#pragma unroll
                for (int j = 0; j < 2; ++j) {
                    mma16816h(acc[i][2 * j],     af[i], bf[j][0], bf[j][2]);
                    mma16816h(acc[i][2 * j + 1], af[i], bf[j][1], bf[j][3]);
                }
        }
        if (lane == 0) MBAR_ARRIVE(smem_u32(&barE[st]));
        if (tid == 0 && k < 4) {
            MBAR_WAIT(smem_u32(&barE[st]), 0);
            uint32_t mb = smem_u32(&barF[st]);
            MBAR_EXPECT(mb, 16384);
            bulk_g2s(base + st * 16384,        F_tiles + ((size_t)(tile * 8 + k + 4)) * 8192, 8192, mb);
            bulk_g2s(base + st * 16384 + 8192, E_tiles + ((size_t)(cblk * 8 + k + 4)) * 8192, 8192, mb);
        }
    }

    // ---- epilogue: CTA-local per-pixel min, then candidate append ----
    const float INF = __int_as_float(0x7f800000);
    float mr[2][2] = { { INF, INF }, { INF, INF } };
#pragma unroll
    for (int i = 0; i < 2; ++i)
#pragma unroll
        for (int j = 0; j < 4; ++j) {
            const int col0 = wn + ((j >> 1) << 4) + ((j & 1) << 3) + (tg << 1);
            const float e0 = s_esq[col0], e1 = s_esq[col0 + 1];
            float2 lo = __half22float2(*reinterpret_cast<__half2*>(&acc[i][j][0]));
            float2 hi = __half22float2(*reinterpret_cast<__half2*>(&acc[i][j][1]));
            mr[i][0] = fminf(mr[i][0], fminf(fmaf(-2.f, lo.x, e0), fmaf(-2.f, lo.y, e1)));
            mr[i][1] = fminf(mr[i][1], fminf(fmaf(-2.f, hi.x, e0), fmaf(-2.f, hi.y, e1)));
        }
#pragma unroll
    for (int i = 0; i < 2; ++i)
#pragma unroll
        for (int h = 0; h < 2; ++h) {
            float m = mr[i][h];
            m = fminf(m, __shfl_xor_sync(0xffffffffu, m, 1));
            m = fminf(m, __shfl_xor_sync(0xffffffffu, m, 2));
            if (tg == 0) atomicMin(&s_pmin[wm + (i << 4) + (h << 3) + g], f2ord(m));
        }
    __syncthreads();

    float thr[2][2];
#pragma unroll
    for (int i = 0; i < 2; ++i)
#pragma unroll
        for (int h = 0; h < 2; ++h)
            thr[i][h] = ord2f(s_pmin[wm + (i << 4) + (h << 3) + g]) + MARGIN;

    const int blk = (tile << 2) + (wid & 3);
#pragma unroll
    for (int i = 0; i < 2; ++i)
#pragma unroll
        for (int j = 0; j < 4; ++j) {
            const int col0 = wn + ((j >> 1) << 4) + ((j & 1) << 3) + (tg << 1);
            const float e0 = s_esq[col0], e1 = s_esq[col0 + 1];
            float2 lo = __half22float2(*reinterpret_cast<__half2*>(&acc[i][j][0]));
            float2 hi = __half22float2(*reinterpret_cast<__half2*>(&acc[i][j][1]));
            float cv[2][2] = { { lo.x, lo.y }, { hi.x, hi.y } };
#pragma unroll
            for (int h = 0; h < 2; ++h) {
                const int lr = (i << 4) + (h << 3) + g;
                float s0 = fmaf(-2.f, cv[h][0], e0);
                float s1 = fmaf(-2.f, cv[h][1], e1);
                if (s0 <= thr[i][h]) {
                    int idx = atomicAdd(&g_ccnt[blk], 1);
                    if (idx < CAP) {
                        g_cand[(size_t)blk * CAP + idx] = ((unsigned)lr << 16) | (unsigned)(n0 + col0);
                        g_csc[(size_t)blk * CAP + idx] = s0;
                    }
                }
                if (s1 <= thr[i][h]) {
                    int idx = atomicAdd(&g_ccnt[blk], 1);
                    if (idx < CAP) {
                        g_cand[(size_t)blk * CAP + idx] = ((unsigned)lr << 16) | (unsigned)(n0 + col0 + 1);
                        g_csc[(size_t)blk * CAP + idx] = s1;
                    }
                }
            }
        }
}

// ---------------- select + exact rescore + gather + output + MSE (R13-verified slim) ----------------
__global__ void __launch_bounds__(256)
k_select(const float* __restrict__ lat, const float* __restrict__ emb,
         float* __restrict__ out) {
    extern __shared__ float sm_f[];    // [256 dims][stride 33]; overwritten by quant in phase 2
    __shared__ unsigned long long s_keys[32];
    __shared__ unsigned s_amin[32];
    __shared__ float s_sf[32];
    __shared__ int sInd[32];

    const int t = threadIdx.x;
    const int b2 = blockIdx.x;
    const int p0g = b2 << 5;
    const int b = p0g >> 10, p0 = p0g & 1023;

    if (t < 32) { s_keys[t] = ~0ULL; s_amin[t] = ~0u; }
#pragma unroll
    for (int i = 0; i < 32; ++i) {
        int d = (i << 3) + (t >> 5), px = t & 31;
        sm_f[d * 33 + px] = lat[(((size_t)(b * 256 + d)) << 10) + p0 + px];
    }
    __syncthreads();

    if (t < 32) {
        float s = 0.f;
#pragma unroll 4
        for (int d = 0; d < DDIM; ++d) { float v = sm_f[d * 33 + t]; s = fmaf(v, v, s); }
        s_sf[t] = s;
    }
    const int cnt = min(g_ccnt[b2], CAP);

    for (int c = t; c < cnt; c += 256) {
        unsigned e = g_cand[(size_t)b2 * CAP + c];
        atomicMin(&s_amin[e >> 16], f2ord(g_csc[(size_t)b2 * CAP + c]));
    }
    __syncthreads();

    for (int c = t; c < cnt; c += 256) {
        unsigned e = g_cand[(size_t)b2 * CAP + c];
        int px = e >> 16, code = e & 1023;
        float ap = g_csc[(size_t)b2 * CAP + c];
        if (ap <= ord2f(s_amin[px]) + MARGIN) {
            const float4* er = reinterpret_cast<const float4*>(emb + ((size_t)code << 8));
            const float* fcol = sm_f + px;
            float a0 = 0.f, a1 = 0.f, a2 = 0.f, a3 = 0.f;
#pragma unroll 8
            for (int d4 = 0; d4 < 64; ++d4) {
                float4 e4 = __ldg(er + d4);
                int d = d4 << 2;
                a0 = fmaf(fcol[(d    ) * 33], e4.x, a0);
                a1 = fmaf(fcol[(d + 1) * 33], e4.y, a1);
                a2 = fmaf(fcol[(d + 2) * 33], e4.z, a2);
                a3 = fmaf(fcol[(d + 3) * 33], e4.w, a3);
            }
            float dot = (a0 + a1) + (a2 + a3);
            float sx = fmaf(-2.f, dot, s_sf[px] + g_esq[code]);  // exact reference chain
            unsigned long long key = ((unsigned long long)f2ord(sx) << 32) | (unsigned)code;
            atomicMin(&s_keys[px], key);
        }
    }
    __syncthreads();

    if (t < 32) sInd[t] = (int)(unsigned)s_keys[t];
    __syncthreads();

    float accl = 0.f;
#pragma unroll
    for (int i = 0; i < 8; ++i) {
        int idx4 = t + (i << 8);
        int r = idx4 >> 6, c4 = (idx4 & 63) << 2;
        float4 q = *(const float4*)(emb + (size_t)sInd[r] * DDIM + c4);
        float l0 = sm_f[(c4    ) * 33 + r];
        float l1 = sm_f[(c4 + 1) * 33 + r];
        float l2 = sm_f[(c4 + 2) * 33 + r];
        float l3 = sm_f[(c4 + 3) * 33 + r];
        float d0 = q.x - l0, d1 = q.y - l1, d2 = q.z - l2, d3 = q.w - l3;
        accl = fmaf(d0, d0, accl); accl = fmaf(d1, d1, accl);
        accl = fmaf(d2, d2, accl); accl = fmaf(d3, d3, accl);
        sm_f[(c4    ) * 33 + r] = q.x;
        sm_f[(c4 + 1) * 33 + r] = q.y;
        sm_f[(c4 + 2) * 33 + r] = q.z;
        sm_f[(c4 + 3) * 33 + r] = q.w;
    }
#pragma unroll
    for (int sh = 16; sh; sh >>= 1) accl += __shfl_xor_sync(0xffffffffu, accl, sh);
    if ((t & 31) == 0) atomicAdd(&g_loss, accl);
    __syncthreads();

    const int i2 = t & 31, db = t >> 5;
#pragma unroll
    for (int dd = 0; dd < 32; ++dd) {
        int d = (dd << 3) + db;
        size_t gi = ((size_t)(b * DDIM + d)) * HW + p0 + i2;
        out[gi] = sm_f[d * 33 + i2];
    }
}

__global__ void k_final(float* __restrict__ out, int off) {
    float S = g_loss * (1.0f / 16777216.0f);
    out[off]     = S;
    out[off + 1] = 0.25f * S;
}

// ---------------- streams/events, created once at static-init (pre-main) ----------------
struct StreamInit {
    cudaStream_t s2;
    cudaEvent_t e0, e1;
    StreamInit() {
        cudaStreamCreateWithFlags(&s2, cudaStreamNonBlocking);
        cudaEventCreateWithFlags(&e0, cudaEventDisableTiming);
        cudaEventCreateWithFlags(&e1, cudaEventDisableTiming);
    }
};
static StreamInit g_si;

extern "C" void kernel_launch(void* const* d_in, const int* in_sizes, int n_in,
                              void* d_out, int out_size) {
    const float* lat = (const float*)d_in[0];
    const float* emb = (const float*)d_in[1];
    float* out = (float*)d_out;

    static const int DYN_SEL = 256 * 33 * 4;   // 33792 B
    static const int DYN_DIST = 4 * 16384;     // 65536 B
    cudaFuncSetAttribute(k_select, cudaFuncAttributeMaxDynamicSharedMemorySize, DYN_SEL);
    cudaFuncSetAttribute(k_dist, cudaFuncAttributeMaxDynamicSharedMemorySize, DYN_DIST);

    // prep fork: small emb-side kernels overlap the big latent transpose
    cudaEventRecord(g_si.e0, 0);
    cudaStreamWaitEvent(g_si.s2, g_si.e0, 0);
    k_esq<<<KCODE / 8, 256, 0, g_si.s2>>>(emb);
    k_prep_emb<<<dim3(8, 8), 256, 0, g_si.s2>>>(emb);
    cudaEventRecord(g_si.e1, g_si.s2);

    k_prep_lat<<<dim3(512, 8), 256>>>(lat);
    cudaStreamWaitEvent(0, g_si.e1, 0);     // join preps

    k_dist<<<dim3(8, 512), 512, DYN_DIST>>>();
    k_select<<<NBLK, 256, DYN_SEL>>>(lat, emb, out);
    if (out_size >= NPIX * DDIM + 2) {
        k_final<<<1, 1>>>(out, out_size - 2);
    }
}

// round 17
// speedup vs baseline: 1.0655x; 1.0499x over previous
#include <cuda_runtime.h>
#include <cuda_bf16.h>
#include <cuda_fp16.h>
#include <cstdint>

#define NPIX  65536
#define KCODE 1024
#define DDIM  256
#define HW    1024
#define MARGIN 1e-3f
#define CAP   1024          // candidate slots per 32-pixel block
#define NBLK  2048          // NPIX / 32

// ---------------- device scratch (static; no allocs) ----------------
__device__ __align__(128) unsigned char F_tiles[(size_t)512 * 8 * 8192];  // 32MB fp16 latent tiles
__device__ __align__(128) unsigned char E_tiles[(size_t)8 * 8 * 8192];    // 512KB fp16 codebook tiles
__device__ unsigned g_cand[(size_t)NBLK * CAP];   // (pix_local<<16)|code
__device__ float    g_csc[(size_t)NBLK * CAP];    // approx score (esq - 2*dot)
__device__ int      g_ccnt[NBLK];
__device__ float    g_esq[KCODE];
__device__ float    g_loss;

// ---------------- helpers ----------------
__device__ __forceinline__ unsigned f2ord(float f) {
    unsigned u = __float_as_uint(f);
    return (u & 0x80000000u) ? ~u : (u | 0x80000000u);
}
__device__ __forceinline__ float ord2f(unsigned u) {
    unsigned v = (u & 0x80000000u) ? (u & 0x7fffffffu) : ~u;
    return __uint_as_float(v);
}
__device__ __forceinline__ uint32_t smem_u32(const void* p) {
    uint32_t a;
    asm("{ .reg .u64 t; cvta.to.shared.u64 t, %1; cvt.u32.u64 %0, t; }" : "=r"(a) : "l"(p));
    return a;
}
__device__ __forceinline__ uint32_t h2(float a, float b) {
    __half2 h = __float22half2_rn(make_float2(a, b));
    return *reinterpret_cast<uint32_t*>(&h);
}
#define SWZ64(off) ((off) ^ (((off) >> 3) & 0x30u))

#define MBAR_INIT(mb, cnt) \
    asm volatile("mbarrier.init.shared.b64 [%0], %1;" :: "r"(mb), "r"((uint32_t)(cnt)) : "memory")
#define MBAR_EXPECT(mb, tx) \
    asm volatile("mbarrier.arrive.expect_tx.shared.b64 _, [%0], %1;" :: "r"(mb), "r"((uint32_t)(tx)) : "memory")
#define MBAR_ARRIVE(mb) \
    asm volatile("mbarrier.arrive.shared.b64 _, [%0];" :: "r"(mb) : "memory")
#define MBAR_WAIT(mb, ph) do {                                                          \
    uint32_t _m = (mb), _p = (ph), _d;                                                  \
    asm volatile("{\n\t.reg .pred p;\n\t"                                               \
        "mbarrier.try_wait.parity.acquire.cta.shared::cta.b64 p, [%1], %2;\n\t"         \
        "selp.b32 %0, 1, 0, p;\n\t}" : "=r"(_d) : "r"(_m), "r"(_p) : "memory");         \
    if (!_d) {                                                                           \
        asm volatile("{\n\t.reg .pred P1;\n\t"                                           \
            "W_%=:\n\t"                                                                  \
            "mbarrier.try_wait.parity.acquire.cta.shared::cta.b64 P1, [%0], %1, 0x989680;\n\t" \
            "@P1 bra.uni D_%=;\n\t"                                                      \
            "bra.uni W_%=;\n\t"                                                          \
            "D_%=:\n\t}" :: "r"(_m), "r"(_p) : "memory");                                \
    }                                                                                    \
} while (0)

__device__ __forceinline__ void bulk_g2s(uint32_t dst, const void* src, uint32_t bytes, uint32_t mb) {
    asm volatile("cp.async.bulk.shared::cta.global.mbarrier::complete_tx::bytes [%0], [%1], %2, [%3];"
                 :: "r"(dst), "l"(src), "r"(bytes), "r"(mb) : "memory");
}
__device__ __forceinline__ void ldsm4(uint32_t* r, uint32_t addr) {
    asm volatile("ldmatrix.sync.aligned.m8n8.x4.shared.b16 {%0,%1,%2,%3}, [%4];"
                 : "=r"(r[0]), "=r"(r[1]), "=r"(r[2]), "=r"(r[3]) : "r"(addr));
}
// fp16 inputs, fp16 accumulate
__device__ __forceinline__ void mma16816h(uint32_t* c, const uint32_t* a, uint32_t b0, uint32_t b1) {
    asm volatile("mma.sync.aligned.m16n8k16.row.col.f16.f16.f16.f16 "
                 "{%0,%1}, {%2,%3,%4,%5}, {%6,%7}, {%0,%1};"
                 : "+r"(c[0]), "+r"(c[1])
                 : "r"(a[0]), "r"(a[1]), "r"(a[2]), "r"(a[3]), "r"(b0), "r"(b1));
}

// ---------------- ||e||^2 + counter init (merged) ----------------
__global__ void k_esq(const float* __restrict__ emb) {
    int gt = blockIdx.x * 256 + threadIdx.x;
    if (gt < NBLK) g_ccnt[gt] = 0;
    if (gt == 0) g_loss = 0.f;
    int w = gt >> 5, lane = gt & 31;
    const float* row = emb + (size_t)w * DDIM;
    float s = 0.f;
#pragma unroll
    for (int j = 0; j < 8; ++j) { float v = row[lane + 32 * j]; s = fmaf(v, v, s); }
#pragma unroll
    for (int sh = 16; sh; sh >>= 1) s += __shfl_xor_sync(0xffffffffu, s, sh);
    if (lane == 0) g_esq[w] = s;
}

// embedding -> blocked swizzled fp16 tiles. grid (8 cblk, 8 kiter), 256 thr.
__global__ void k_prep_emb(const float* __restrict__ emb) {
    int c0 = blockIdx.x << 7, d0 = blockIdx.y << 5;
    unsigned char* dst = E_tiles + ((size_t)(blockIdx.x * 8 + blockIdx.y)) * 8192;
    int t = threadIdx.x;
#pragma unroll
    for (int i = 0; i < 2; ++i) {
        int u = t + (i << 8);
        int r = u >> 2, c8 = (u & 3) << 3;
        const float* src = emb + (size_t)(c0 + r) * DDIM + d0 + c8;
        float4 v0 = *(const float4*)src;
        float4 v1 = *(const float4*)(src + 4);
        uint4 o;
        o.x = h2(v0.x, v0.y); o.y = h2(v0.z, v0.w);
        o.z = h2(v1.x, v1.y); o.w = h2(v1.z, v1.w);
        *(uint4*)(dst + SWZ64((uint32_t)(u << 4))) = o;
    }
}

// latents -> transposed blocked swizzled fp16 tiles. grid (512 tiles, 8 kiter).
__global__ void k_prep_lat(const float* __restrict__ lat) {
    __shared__ float ts[32][129];
    int tile = blockIdx.x, kit = blockIdx.y;
    int b = tile >> 3, p0 = (tile & 7) << 7, d0 = kit << 5;
    int t = threadIdx.x;
#pragma unroll
    for (int i = 0; i < 4; ++i) {
        int u = t + (i << 8);
        int r = u >> 5, c4 = (u & 31) << 2;
        float4 v = *(const float4*)(lat + (((size_t)(b * 256 + d0 + r)) << 10) + p0 + c4);
        ts[r][c4] = v.x; ts[r][c4 + 1] = v.y; ts[r][c4 + 2] = v.z; ts[r][c4 + 3] = v.w;
    }
    __syncthreads();
    unsigned char* dst = F_tiles + ((size_t)(tile * 8 + kit)) * 8192;
#pragma unroll
    for (int i = 0; i < 2; ++i) {
        int u = t + (i << 8);
        int p = u >> 2, c8 = (u & 3) << 3;
        uint4 o;
        o.x = h2(ts[c8][p],     ts[c8 + 1][p]);
        o.y = h2(ts[c8 + 2][p], ts[c8 + 3][p]);
        o.z = h2(ts[c8 + 4][p], ts[c8 + 5][p]);
        o.w = h2(ts[c8 + 6][p], ts[c8 + 7][p]);
        *(uint4*)(dst + SWZ64((uint32_t)(u << 4))) = o;
    }
}

// ---------------- fp16 HMMA GEMM: 16 warps/CTA (32x32 warp tiles), 4-stage pipeline (R13-verified) ----------------
__global__ void __launch_bounds__(512, 2)
k_dist() {
    extern __shared__ __align__(128) unsigned char buf[];   // 4 x 16384
    __shared__ __align__(8) unsigned long long barF[4];
    __shared__ __align__(8) unsigned long long barE[4];
    __shared__ float s_esq[128];
    __shared__ unsigned s_pmin[128];

    const int tid = threadIdx.x;
    const int lane = tid & 31, wid = tid >> 5;          // 16 warps
    const int cblk = blockIdx.x, tile = blockIdx.y;
    const int n0 = cblk << 7;
    const int wm = (wid & 3) << 5, wn = (wid >> 2) << 5; // 4x4 warp grid, 32x32 tiles
    const int rl = lane & 15;
    const uint32_t ch = (uint32_t)((lane >> 4) << 4);
    const int g = lane >> 2, tg = lane & 3;

    uint32_t qa[2], qb[2];
#pragma unroll
    for (int i = 0; i < 2; ++i) {
        uint32_t row = (uint32_t)(wm + (i << 4) + rl);
        qa[i] = ((row << 6) ^ ((row & 6u) << 3)) ^ ch;
    }
#pragma unroll
    for (int j = 0; j < 2; ++j) {
        uint32_t row = (uint32_t)(wn + (j << 4) + rl);
        qb[j] = ((row << 6) ^ ((row & 6u) << 3)) ^ ch;
    }

    if (tid < 128) { s_esq[tid] = g_esq[n0 + tid]; s_pmin[tid] = ~0u; }
    if (tid == 0) {
#pragma unroll
        for (int s = 0; s < 4; ++s) {
            MBAR_INIT(smem_u32(&barF[s]), 1);
            MBAR_INIT(smem_u32(&barE[s]), 16);
        }
    }
    __syncthreads();
    const uint32_t base = smem_u32(buf);
    if (tid == 0) {
#pragma unroll
        for (int s = 0; s < 4; ++s) {
            uint32_t mb = smem_u32(&barF[s]);
            MBAR_EXPECT(mb, 16384);
            bulk_g2s(base + s * 16384,        F_tiles + ((size_t)(tile * 8 + s)) * 8192, 8192, mb);
            bulk_g2s(base + s * 16384 + 8192, E_tiles + ((size_t)(cblk * 8 + s)) * 8192, 8192, mb);
        }
    }

    uint32_t acc[2][4][2];
#pragma unroll
    for (int i = 0; i < 2; ++i)
#pragma unroll
        for (int j = 0; j < 4; ++j) { acc[i][j][0] = 0u; acc[i][j][1] = 0u; }

    for (int k = 0; k < 8; ++k) {
        const int st = k & 3;
        MBAR_WAIT(smem_u32(&barF[st]), (k >> 2) & 1);
        const uint32_t As = base + st * 16384;
#pragma unroll
        for (int s = 0; s < 2; ++s) {
            const uint32_t soff = (uint32_t)(s << 5);
            uint32_t af[2][4], bf[2][4];
#pragma unroll
            for (int i = 0; i < 2; ++i) ldsm4(af[i], As + (qa[i] ^ soff));
#pragma unroll
            for (int j = 0; j < 2; ++j) ldsm4(bf[j], As + 8192 + (qb[j] ^ soff));
#pragma unroll
            for (int i = 0; i < 2; ++i)
#pragma unroll
                for (int j = 0; j < 2; ++j) {
                    mma16816h(acc[i][2 * j],     af[i], bf[j][0], bf[j][2]);
                    mma16816h(acc[i][2 * j + 1], af[i], bf[j][1], bf[j][3]);
                }
        }
        if (lane == 0) MBAR_ARRIVE(smem_u32(&barE[st]));
        if (tid == 0 && k < 4) {
            MBAR_WAIT(smem_u32(&barE[st]), 0);
            uint32_t mb = smem_u32(&barF[st]);
            MBAR_EXPECT(mb, 16384);
            bulk_g2s(base + st * 16384,        F_tiles + ((size_t)(tile * 8 + k + 4)) * 8192, 8192, mb);
            bulk_g2s(base + st * 16384 + 8192, E_tiles + ((size_t)(cblk * 8 + k + 4)) * 8192, 8192, mb);
        }
    }

    // ---- epilogue: CTA-local per-pixel min, then candidate append ----
    const float INF = __int_as_float(0x7f800000);
    float mr[2][2] = { { INF, INF }, { INF, INF } };
#pragma unroll
    for (int i = 0; i < 2; ++i)
#pragma unroll
        for (int j = 0; j < 4; ++j) {
            const int col0 = wn + ((j >> 1) << 4) + ((j & 1) << 3) + (tg << 1);
            const float e0 = s_esq[col0], e1 = s_esq[col0 + 1];
            float2 lo = __half22float2(*reinterpret_cast<__half2*>(&acc[i][j][0]));
            float2 hi = __half22float2(*reinterpret_cast<__half2*>(&acc[i][j][1]));
            mr[i][0] = fminf(mr[i][0], fminf(fmaf(-2.f, lo.x, e0), fmaf(-2.f, lo.y, e1)));
            mr[i][1] = fminf(mr[i][1], fminf(fmaf(-2.f, hi.x, e0), fmaf(-2.f, hi.y, e1)));
        }
#pragma unroll
    for (int i = 0; i < 2; ++i)
#pragma unroll
        for (int h = 0; h < 2; ++h) {
            float m = mr[i][h];
            m = fminf(m, __shfl_xor_sync(0xffffffffu, m, 1));
            m = fminf(m, __shfl_xor_sync(0xffffffffu, m, 2));
            if (tg == 0) atomicMin(&s_pmin[wm + (i << 4) + (h << 3) + g], f2ord(m));
        }
    __syncthreads();

    float thr[2][2];
#pragma unroll
    for (int i = 0; i < 2; ++i)
#pragma unroll
        for (int h = 0; h < 2; ++h)
            thr[i][h] = ord2f(s_pmin[wm + (i << 4) + (h << 3) + g]) + MARGIN;

    const int blk = (tile << 2) + (wid & 3);
#pragma unroll
    for (int i = 0; i < 2; ++i)
#pragma unroll
        for (int j = 0; j < 4; ++j) {
            const int col0 = wn + ((j >> 1) << 4) + ((j & 1) << 3) + (tg << 1);
            const float e0 = s_esq[col0], e1 = s_esq[col0 + 1];
            float2 lo = __half22float2(*reinterpret_cast<__half2*>(&acc[i][j][0]));
            float2 hi = __half22float2(*reinterpret_cast<__half2*>(&acc[i][j][1]));
            float cv[2][2] = { { lo.x, lo.y }, { hi.x, hi.y } };
#pragma unroll
            for (int h = 0; h < 2; ++h) {
                const int lr = (i << 4) + (h << 3) + g;
                float s0 = fmaf(-2.f, cv[h][0], e0);
                float s1 = fmaf(-2.f, cv[h][1], e1);
                if (s0 <= thr[i][h]) {
                    int idx = atomicAdd(&g_ccnt[blk], 1);
                    if (idx < CAP) {
                        g_cand[(size_t)blk * CAP + idx] = ((unsigned)lr << 16) | (unsigned)(n0 + col0);
                        g_csc[(size_t)blk * CAP + idx] = s0;
                    }
                }
                if (s1 <= thr[i][h]) {
                    int idx = atomicAdd(&g_ccnt[blk], 1);
                    if (idx < CAP) {
                        g_cand[(size_t)blk * CAP + idx] = ((unsigned)lr << 16) | (unsigned)(n0 + col0 + 1);
                        g_csc[(size_t)blk * CAP + idx] = s1;
                    }
                }
            }
        }
}

// ---------------- select + exact rescore + gather + output + MSE (512 threads) ----------------
__global__ void __launch_bounds__(512)
k_select(const float* __restrict__ lat, const float* __restrict__ emb,
         float* __restrict__ out) {
    extern __shared__ float sm_f[];    // [256 dims][stride 33]; overwritten by quant in phase 2
    __shared__ unsigned long long s_keys[32];
    __shared__ unsigned s_amin[32];
    __shared__ float s_sf[32];
    __shared__ int sInd[32];

    const int t = threadIdx.x;
    const int b2 = blockIdx.x;
    const int p0g = b2 << 5;
    const int b = p0g >> 10, p0 = p0g & 1023;

    if (t < 32) { s_keys[t] = ~0ULL; s_amin[t] = ~0u; }
#pragma unroll
    for (int i = 0; i < 16; ++i) {
        int d = (i << 4) + (t >> 5), px = t & 31;    // t>>5 in 0..15
        sm_f[d * 33 + px] = lat[(((size_t)(b * 256 + d)) << 10) + p0 + px];
    }
    __syncthreads();

    // ||f||^2 with the IDENTICAL serial chain as verified rounds
    if (t < 32) {
        float s = 0.f;
#pragma unroll 4
        for (int d = 0; d < DDIM; ++d) { float v = sm_f[d * 33 + t]; s = fmaf(v, v, s); }
        s_sf[t] = s;
    }
    const int cnt = min(g_ccnt[b2], CAP);

    // pass A: global approx min per pixel
    for (int c = t; c < cnt; c += 512) {
        unsigned e = g_cand[(size_t)b2 * CAP + c];
        atomicMin(&s_amin[e >> 16], f2ord(g_csc[(size_t)b2 * CAP + c]));
    }
    __syncthreads();

    // pass B: exact rescore of candidates within margin (reads sm_f latents)
    for (int c = t; c < cnt; c += 512) {
        unsigned e = g_cand[(size_t)b2 * CAP + c];
        int px = e >> 16, code = e & 1023;
        float ap = g_csc[(size_t)b2 * CAP + c];
        if (ap <= ord2f(s_amin[px]) + MARGIN) {
            const float4* er = reinterpret_cast<const float4*>(emb + ((size_t)code << 8));
            const float* fcol = sm_f + px;
            float a0 = 0.f, a1 = 0.f, a2 = 0.f, a3 = 0.f;
#pragma unroll 8
            for (int d4 = 0; d4 < 64; ++d4) {
                float4 e4 = __ldg(er + d4);
                int d = d4 << 2;
                a0 = fmaf(fcol[(d    ) * 33], e4.x, a0);
                a1 = fmaf(fcol[(d + 1) * 33], e4.y, a1);
                a2 = fmaf(fcol[(d + 2) * 33], e4.z, a2);
                a3 = fmaf(fcol[(d + 3) * 33], e4.w, a3);
            }
            float dot = (a0 + a1) + (a2 + a3);
            float sx = fmaf(-2.f, dot, s_sf[px] + g_esq[code]);  // exact reference chain
            unsigned long long key = ((unsigned long long)f2ord(sx) << 32) | (unsigned)code;
            atomicMin(&s_keys[px], key);
        }
    }
    __syncthreads();

    if (t < 32) sInd[t] = (int)(unsigned)s_keys[t];
    __syncthreads();

    // phase 2: gather winners' rows, fused MSE vs latent, overwrite sm_f with quant
    float accl = 0.f;
#pragma unroll
    for (int i = 0; i < 4; ++i) {
        int idx4 = t + (i << 9);                      // 4 x 512 = 2048 units
        int r = idx4 >> 6, c4 = (idx4 & 63) << 2;     // r = pixel, c4 = dim base
        float4 q = *(const float4*)(emb + (size_t)sInd[r] * DDIM + c4);
        float l0 = sm_f[(c4    ) * 33 + r];
        float l1 = sm_f[(c4 + 1) * 33 + r];
        float l2 = sm_f[(c4 + 2) * 33 + r];
        float l3 = sm_f[(c4 + 3) * 33 + r];
        float d0 = q.x - l0, d1 = q.y - l1, d2 = q.z - l2, d3 = q.w - l3;
        accl = fmaf(d0, d0, accl); accl = fmaf(d1, d1, accl);
        accl = fmaf(d2, d2, accl); accl = fmaf(d3, d3, accl);
        sm_f[(c4    ) * 33 + r] = q.x;
        sm_f[(c4 + 1) * 33 + r] = q.y;
        sm_f[(c4 + 2) * 33 + r] = q.z;
        sm_f[(c4 + 3) * 33 + r] = q.w;
    }
#pragma unroll
    for (int sh = 16; sh; sh >>= 1) accl += __shfl_xor_sync(0xffffffffu, accl, sh);
    if ((t & 31) == 0) atomicAdd(&g_loss, accl);
    __syncthreads();

    // phase 3: transposed coalesced output from sm_f (now quant)
    const int i2 = t & 31, db = t >> 5;               // db in 0..15
#pragma unroll
    for (int dd = 0; dd < 16; ++dd) {
        int d = (dd << 4) + db;
        size_t gi = ((size_t)(b * DDIM + d)) * HW + p0 + i2;
        out[gi] = sm_f[d * 33 + i2];
    }
}

__global__ void k_final(float* __restrict__ out, int off) {
    float S = g_loss * (1.0f / 16777216.0f);
    out[off]     = S;
    out[off + 1] = 0.25f * S;
}

extern "C" void kernel_launch(void* const* d_in, const int* in_sizes, int n_in,
                              void* d_out, int out_size) {
    const float* lat = (const float*)d_in[0];
    const float* emb = (const float*)d_in[1];
    float* out = (float*)d_out;

    static const int DYN_SEL = 256 * 33 * 4;   // 33792 B
    static const int DYN_DIST = 4 * 16384;     // 65536 B
    cudaFuncSetAttribute(k_select, cudaFuncAttributeMaxDynamicSharedMemorySize, DYN_SEL);
    cudaFuncSetAttribute(k_dist, cudaFuncAttributeMaxDynamicSharedMemorySize, DYN_DIST);

    k_esq<<<KCODE / 8, 256>>>(emb);
    k_prep_emb<<<dim3(8, 8), 256>>>(emb);
    k_prep_lat<<<dim3(512, 8), 256>>>(lat);
    k_dist<<<dim3(8, 512), 512, DYN_DIST>>>();
    k_select<<<NBLK, 512, DYN_SEL>>>(lat, emb, out);
    if (out_size >= NPIX * DDIM + 2) {
        k_final<<<1, 1>>>(out, out_size - 2);
    }
}